// round 5
// baseline (speedup 1.0000x reference)
#include <cuda_runtime.h>

#define N_CHROM 23
#define BINS    5000
#define NB      16
#define NS      512
#define EOS_DIM 512
#define BIN_DIM 256
#define VOCAB   (N_CHROM * BINS)        // 115000
#define NSAMP   (N_CHROM * NB * NS)     // 188416
#define OCC     3
#define GRID    (148 * OCC)             // 444, all co-resident
#define TROWS   16                      // rows per tile (16 KB)
#define NTILES  ((VOCAB + TROWS - 1) / TROWS)   // 7188 (last tile: 8 rows)
#define EOS_B0  (GRID - 46)             // eos on high block ids

// ---- scratch (device globals) ----
__device__ __align__(16) float g_M[3 * BIN_DIM];     // W_fc1 @ W_bin  [3,256]
__device__ __align__(16) float g_Meos[3 * EOS_DIM];  // W_fc2 @ W_eos  [3,512]
__device__ float    g_cbias[4];
__device__ float4   g_E[NB * N_CHROM];
__device__ float4   g_P[VOCAB];
__device__ unsigned g_bar;              // monotone barrier counter (zero-init)

__device__ __forceinline__ void grid_bar(unsigned target) {
    __syncthreads();
    if (threadIdx.x == 0) {
        __threadfence();
        unsigned prev = atomicAdd(&g_bar, 1u);
        if (prev + 1u < target) {
            while (*(volatile unsigned*)&g_bar < target) __nanosleep(32);
        }
        __threadfence();
    }
    __syncthreads();
}

__device__ __forceinline__ void cpa16(float4* smem_dst, const float4* gsrc, bool pred) {
    unsigned sa = (unsigned)__cvta_generic_to_shared(smem_dst);
    if (pred)
        asm volatile("cp.async.cg.shared.global [%0], [%1], 16;\n" :: "r"(sa), "l"(gsrc));
}
#define CPA_COMMIT() asm volatile("cp.async.commit_group;\n" ::: "memory")
#define CPA_WAIT1()  asm volatile("cp.async.wait_group 1;\n" ::: "memory")

__global__ void __launch_bounds__(256, OCC)
k_fused(const float*  __restrict__ eos_emb,   // [16,23,512]
        const int4*   __restrict__ sampled,   // [23,16,512] as quads
        const int4*   __restrict__ targets,
        const float4* __restrict__ tbl,       // [115000,64] float4
        const float*  __restrict__ Wbin,      // [512,256]
        const float*  __restrict__ Weos,      // [512,512]
        const float*  __restrict__ beos,      // [512]
        const float*  __restrict__ Wfc,       // [3,1024]
        const float*  __restrict__ bfc,       // [3]
        float* __restrict__ out,
        int write_targets) {
    const int bid  = blockIdx.x;
    const int tid  = threadIdx.x;
    const int lane = tid & 31;
    const int warp = tid >> 5;

    __shared__ float  s[3][8][32];
    __shared__ float4 sbuf[2][TROWS * 64];   // 2 x 16 KB table tiles

    // ---- cp.async prologue: start streaming the table immediately ----
    const int cnt = (NTILES - 1 - bid) / GRID + 1;   // tiles for this block (>=16)
    {
        size_t base = (size_t)bid * (TROWS * 64) + tid;
#pragma unroll
        for (int k2 = 0; k2 < 4; k2++)
            cpa16(&sbuf[0][tid + k2 * 256], tbl + base + k2 * 256,
                  base + k2 * 256 < (size_t)VOCAB * 64);
        CPA_COMMIT();
        if (cnt > 1) {
            size_t b1 = base + (size_t)GRID * (TROWS * 64);
#pragma unroll
            for (int k2 = 0; k2 < 4; k2++)
                cpa16(&sbuf[1][tid + k2 * 256], tbl + b1 + k2 * 256,
                      b1 + k2 * 256 < (size_t)VOCAB * 64);
        }
        CPA_COMMIT();
    }

    // ================= Phase 0: fold the weight chain =================
    if (bid < 24) {
        bool is_eos = (bid < 16);
        int  e      = (is_eos ? bid * 32 : (bid - 16) * 32) + lane;
        int  stride = is_eos ? 512 : 256;
        const float* W = is_eos ? Weos : Wbin;
        int  fc     = is_eos ? 512 : 0;

        float a0 = 0.f, a1 = 0.f, a2 = 0.f;
        int dbeg = warp * 64;
#pragma unroll 16
        for (int d = dbeg; d < dbeg + 64; d++) {
            float w = W[d * stride + e];
            a0 += __ldg(&Wfc[fc + d])        * w;
            a1 += __ldg(&Wfc[1024 + fc + d]) * w;
            a2 += __ldg(&Wfc[2048 + fc + d]) * w;
        }
        s[0][warp][lane] = a0;
        s[1][warp][lane] = a1;
        s[2][warp][lane] = a2;
        __syncthreads();
#pragma unroll
        for (int off = 4; off; off >>= 1) {
            if (warp < off) {
                s[0][warp][lane] += s[0][warp + off][lane];
                s[1][warp][lane] += s[1][warp + off][lane];
                s[2][warp][lane] += s[2][warp + off][lane];
            }
            __syncthreads();
        }
        if (warp == 0) {
            if (is_eos) {
                g_Meos[e]        = s[0][0][lane];
                g_Meos[512 + e]  = s[1][0][lane];
                g_Meos[1024 + e] = s[2][0][lane];
            } else {
                g_M[e]           = s[0][0][lane];
                g_M[256 + e]     = s[1][0][lane];
                g_M[512 + e]     = s[2][0][lane];
            }
        }
    } else if (bid == 24 && tid < 32) {
        float a0 = 0.f, a1 = 0.f, a2 = 0.f;
#pragma unroll
        for (int d = lane; d < 512; d += 32) {
            float v = beos[d];
            a0 += Wfc[512 + d]        * v;
            a1 += Wfc[1024 + 512 + d] * v;
            a2 += Wfc[2048 + 512 + d] * v;
        }
#pragma unroll
        for (int o = 16; o; o >>= 1) {
            a0 += __shfl_down_sync(0xffffffffu, a0, o);
            a1 += __shfl_down_sync(0xffffffffu, a1, o);
            a2 += __shfl_down_sync(0xffffffffu, a2, o);
        }
        if (lane == 0) {
            g_cbias[0] = a0 + bfc[0];
            g_cbias[1] = a1 + bfc[1];
            g_cbias[2] = a2 + bfc[2];
        }
    }

    grid_bar(GRID);   // ---- barrier A: g_M / g_Meos / g_cbias ready ----

    // ================= Phase 1a: eos dot (high blocks) =================
    if (bid >= EOS_B0) {
        int w = (bid - EOS_B0) * 8 + warp;   // 0..367 = b*23 + c
        const float4* row = reinterpret_cast<const float4*>(eos_emb + (size_t)w * EOS_DIM);
        const float4* M0  = reinterpret_cast<const float4*>(g_Meos);
        const float4* M1  = reinterpret_cast<const float4*>(g_Meos + EOS_DIM);
        const float4* M2  = reinterpret_cast<const float4*>(g_Meos + 2 * EOS_DIM);
        float s0 = 0.f, s1 = 0.f, s2 = 0.f;
#pragma unroll
        for (int i = lane; i < EOS_DIM / 4; i += 32) {
            float4 x = row[i];
            float4 m0 = M0[i], m1 = M1[i], m2 = M2[i];
            s0 += x.x*m0.x + x.y*m0.y + x.z*m0.z + x.w*m0.w;
            s1 += x.x*m1.x + x.y*m1.y + x.z*m1.z + x.w*m1.w;
            s2 += x.x*m2.x + x.y*m2.y + x.z*m2.z + x.w*m2.w;
        }
#pragma unroll
        for (int o = 16; o; o >>= 1) {
            s0 += __shfl_down_sync(0xffffffffu, s0, o);
            s1 += __shfl_down_sync(0xffffffffu, s1, o);
            s2 += __shfl_down_sync(0xffffffffu, s2, o);
        }
        if (lane == 0)
            g_E[w] = make_float4(s0 + g_cbias[0], s1 + g_cbias[1], s2 + g_cbias[2], 0.f);
    }

    // ===== Phase 1b: table sweep — cp.async pipeline, M in registers =====
    {
        const int k = lane & 15;            // lane within row
        const int j = lane >> 4;            // row within warp (0/1)
        const int row_local = warp * 2 + j; // 0..15

        // lane-private slice of M: chunks {k, k+16, k+32, k+48} for n=0..2
        float4 m[3][4];
        const float4* gM4 = reinterpret_cast<const float4*>(g_M);
#pragma unroll
        for (int n = 0; n < 3; n++)
#pragma unroll
            for (int s2 = 0; s2 < 4; s2++)
                m[n][s2] = gM4[n * 64 + k + s2 * 16];

        for (int i = 0; i < cnt; i++) {
            const int t = bid + i * GRID;
            CPA_WAIT1();                    // tile i landed (only tile i+1 pending)
            __syncthreads();

            const float4* rowp = &sbuf[i & 1][row_local * 64];
            float a0 = 0.f, a1 = 0.f, a2 = 0.f;
#pragma unroll
            for (int s2 = 0; s2 < 4; s2++) {
                float4 x = rowp[k + s2 * 16];
                a0 += x.x*m[0][s2].x + x.y*m[0][s2].y + x.z*m[0][s2].z + x.w*m[0][s2].w;
                a1 += x.x*m[1][s2].x + x.y*m[1][s2].y + x.z*m[1][s2].z + x.w*m[1][s2].w;
                a2 += x.x*m[2][s2].x + x.y*m[2][s2].y + x.z*m[2][s2].z + x.w*m[2][s2].w;
            }
#pragma unroll
            for (int o = 8; o; o >>= 1) {   // reduce within 16-lane row groups
                a0 += __shfl_xor_sync(0xffffffffu, a0, o);
                a1 += __shfl_xor_sync(0xffffffffu, a1, o);
                a2 += __shfl_xor_sync(0xffffffffu, a2, o);
            }
            int row_global = t * TROWS + row_local;
            if (k == 0 && row_global < VOCAB)
                g_P[row_global] = make_float4(a0, a1, a2, 0.f);

            __syncthreads();                // everyone done reading this stage
            if (i + 2 < cnt) {
                size_t nb = (size_t)(bid + (i + 2) * GRID) * (TROWS * 64) + tid;
#pragma unroll
                for (int k2 = 0; k2 < 4; k2++)
                    cpa16(&sbuf[i & 1][tid + k2 * 256], tbl + nb + k2 * 256,
                          nb + k2 * 256 < (size_t)VOCAB * 64);
            }
            CPA_COMMIT();                   // uniform group accounting
        }
    }

    grid_bar(2 * GRID);   // ---- barrier B: g_P / g_E ready ----

    // ================= Phase 2: gather + relu + emit ==================
    {
        int q = bid * 107 + tid;
        if (tid < 107 && q < NSAMP / 4) {
            int i = q * 4;
            int c = i / (NB * NS);
            int b = (i - c * (NB * NS)) / NS;

            int4 sv = sampled[q];
            int  vb = c * BINS;
            float4 p0 = g_P[vb + sv.x];
            float4 p1 = g_P[vb + sv.y];
            float4 p2 = g_P[vb + sv.z];
            float4 p3 = g_P[vb + sv.w];
            float4 e  = g_E[b * N_CHROM + c];

            float4* o4 = reinterpret_cast<float4*>(out + 12 * (size_t)q);
            o4[0] = make_float4(fmaxf(p0.x + e.x, 0.f), fmaxf(p0.y + e.y, 0.f),
                                fmaxf(p0.z + e.z, 0.f), fmaxf(p1.x + e.x, 0.f));
            o4[1] = make_float4(fmaxf(p1.y + e.y, 0.f), fmaxf(p1.z + e.z, 0.f),
                                fmaxf(p2.x + e.x, 0.f), fmaxf(p2.y + e.y, 0.f));
            o4[2] = make_float4(fmaxf(p2.z + e.z, 0.f), fmaxf(p3.x + e.x, 0.f),
                                fmaxf(p3.y + e.y, 0.f), fmaxf(p3.z + e.z, 0.f));

            if (write_targets) {
                int4 tv = targets[q];
                reinterpret_cast<float4*>(out + 3 * NSAMP)[q] =
                    make_float4((float)tv.x, (float)tv.y, (float)tv.z, (float)tv.w);
            }
        }
    }

    // ---- final arrive: last arrival resets counter for graph replay ----
    __syncthreads();
    if (tid == 0) {
        unsigned prev = atomicAdd(&g_bar, 1u);
        if (prev + 1u == 3u * GRID) atomicExch(&g_bar, 0u);
    }
}

// ---------------------------------------------------------------------------
extern "C" void kernel_launch(void* const* d_in, const int* in_sizes, int n_in,
                              void* d_out, int out_size) {
    const float*  eos_emb = (const float*) d_in[0];
    const int4*   sampled = (const int4*)  d_in[1];
    const int4*   targets = (const int4*)  d_in[2];
    const float4* tbl     = (const float4*)d_in[3];
    const float*  Wbin    = (const float*) d_in[4];
    const float*  Weos    = (const float*) d_in[5];
    const float*  beos    = (const float*) d_in[6];
    const float*  Wfc     = (const float*) d_in[7];
    const float*  bfc     = (const float*) d_in[8];
    float* out = (float*)d_out;

    int write_targets = (out_size >= 4 * NSAMP) ? 1 : 0;
    k_fused<<<GRID, 256>>>(eos_emb, sampled, targets, tbl,
                           Wbin, Weos, beos, Wfc, bfc, out, write_targets);
}

// round 7
// speedup vs baseline: 1.0265x; 1.0265x over previous
#include <cuda_runtime.h>

#define N_CHROM 23
#define BINS    5000
#define NB      16
#define NS      512
#define EOS_DIM 512
#define BIN_DIM 256
#define VOCAB   (N_CHROM * BINS)        // 115000
#define NSAMP   (N_CHROM * NB * NS)     // 188416
#define OCC     3
#define GRID    (148 * OCC)             // 444
#define NWARPS  (GRID * 8)              // 3552
#define NUNITS  (VOCAB / 2)             // 57500 two-row units
#define EOS_B0  (GRID - 46)             // eos on high block ids

// ---- scratch (device globals) ----
__device__ __align__(16) float g_M[3 * BIN_DIM];     // W_fc1 @ W_bin  [3,256]
__device__ __align__(16) float g_Meos[3 * EOS_DIM];  // W_fc2 @ W_eos  [3,512]
__device__ float    g_cbias[4];
__device__ float4   g_E[NB * N_CHROM];
__device__ float4   g_P[VOCAB];
__device__ unsigned g_bar;              // monotone barrier counter (zero-init)

__device__ __forceinline__ void grid_bar(unsigned target) {
    __syncthreads();
    if (threadIdx.x == 0) {
        __threadfence();
        unsigned prev = atomicAdd(&g_bar, 1u);
        if (prev + 1u < target) {
            while (*(volatile unsigned*)&g_bar < target) __nanosleep(32);
        }
        __threadfence();
    }
    __syncthreads();
}

__device__ __forceinline__ float dot8(float4 a, float4 b, float4 m, float4 mb) {
    return a.x*m.x + a.y*m.y + a.z*m.z + a.w*m.w
         + b.x*mb.x + b.y*mb.y + b.z*mb.z + b.w*mb.w;
}

__global__ void __launch_bounds__(256, OCC)
k_fused(const float*  __restrict__ eos_emb,   // [16,23,512]
        const int4*   __restrict__ sampled,   // [23,16,512] as quads
        const int4*   __restrict__ targets,
        const float4* __restrict__ tbl,       // [115000,64] float4
        const float*  __restrict__ Wbin,      // [512,256]
        const float*  __restrict__ Weos,      // [512,512]
        const float*  __restrict__ beos,      // [512]
        const float*  __restrict__ Wfc,       // [3,1024]
        const float*  __restrict__ bfc,       // [3]
        float* __restrict__ out,
        int write_targets) {
    const int bid  = blockIdx.x;
    const int tid  = threadIdx.x;
    const int lane = tid & 31;
    const int warp = tid >> 5;
    const int gw   = bid * 8 + warp;            // 0..3551

    __shared__ float s[3][8][32];

    // ---- early loads: first sweep unit in flight before/through prep ----
    const int cnt = (NUNITS - 1 - gw) / NWARPS + 1;   // 16 or 17
    float4 A0, A1, A2, A3;
    {
        const float4* b0 = tbl + (size_t)gw * 128;
        A0 = __ldcs(b0 + lane);
        A1 = __ldcs(b0 + 32 + lane);
        A2 = __ldcs(b0 + 64 + lane);
        A3 = __ldcs(b0 + 96 + lane);
    }

    // ================= Phase 0: fold the weight chain =================
    if (bid < 24) {
        bool is_eos = (bid < 16);
        int  e      = (is_eos ? bid * 32 : (bid - 16) * 32) + lane;
        int  stride = is_eos ? 512 : 256;
        const float* W = is_eos ? Weos : Wbin;
        int  fc     = is_eos ? 512 : 0;

        float a0 = 0.f, a1 = 0.f, a2 = 0.f;
        int dbeg = warp * 64;
#pragma unroll 16
        for (int d = dbeg; d < dbeg + 64; d++) {
            float w = W[d * stride + e];
            a0 += __ldg(&Wfc[fc + d])        * w;   // Wfc is a true input: nc OK
            a1 += __ldg(&Wfc[1024 + fc + d]) * w;
            a2 += __ldg(&Wfc[2048 + fc + d]) * w;
        }
        s[0][warp][lane] = a0;
        s[1][warp][lane] = a1;
        s[2][warp][lane] = a2;
        __syncthreads();
#pragma unroll
        for (int off = 4; off; off >>= 1) {
            if (warp < off) {
                s[0][warp][lane] += s[0][warp + off][lane];
                s[1][warp][lane] += s[1][warp + off][lane];
                s[2][warp][lane] += s[2][warp + off][lane];
            }
            __syncthreads();
        }
        if (warp == 0) {
            if (is_eos) {
                g_Meos[e]        = s[0][0][lane];
                g_Meos[512 + e]  = s[1][0][lane];
                g_Meos[1024 + e] = s[2][0][lane];
            } else {
                g_M[e]           = s[0][0][lane];
                g_M[256 + e]     = s[1][0][lane];
                g_M[512 + e]     = s[2][0][lane];
            }
        }
    } else if (bid == 24 && tid < 32) {
        float a0 = 0.f, a1 = 0.f, a2 = 0.f;
#pragma unroll
        for (int d = lane; d < 512; d += 32) {
            float v = beos[d];
            a0 += Wfc[512 + d]        * v;
            a1 += Wfc[1024 + 512 + d] * v;
            a2 += Wfc[2048 + 512 + d] * v;
        }
#pragma unroll
        for (int o = 16; o; o >>= 1) {
            a0 += __shfl_down_sync(0xffffffffu, a0, o);
            a1 += __shfl_down_sync(0xffffffffu, a1, o);
            a2 += __shfl_down_sync(0xffffffffu, a2, o);
        }
        if (lane == 0) {
            g_cbias[0] = a0 + bfc[0];
            g_cbias[1] = a1 + bfc[1];
            g_cbias[2] = a2 + bfc[2];
        }
    }

    grid_bar(GRID);   // ---- barrier A: g_M / g_Meos / g_cbias ready ----

    // ================= Phase 1a: eos dot (high blocks) =================
    if (bid >= EOS_B0) {
        int w = (bid - EOS_B0) * 8 + warp;   // 0..367 = b*23 + c
        const float4* row = reinterpret_cast<const float4*>(eos_emb + (size_t)w * EOS_DIM);
        const float4* M0  = reinterpret_cast<const float4*>(g_Meos);
        const float4* M1  = reinterpret_cast<const float4*>(g_Meos + EOS_DIM);
        const float4* M2  = reinterpret_cast<const float4*>(g_Meos + 2 * EOS_DIM);
        float s0 = 0.f, s1 = 0.f, s2 = 0.f;
#pragma unroll
        for (int i = lane; i < EOS_DIM / 4; i += 32) {
            float4 x = row[i];
            float4 m0 = M0[i], m1 = M1[i], m2 = M2[i];
            s0 += x.x*m0.x + x.y*m0.y + x.z*m0.z + x.w*m0.w;
            s1 += x.x*m1.x + x.y*m1.y + x.z*m1.z + x.w*m1.w;
            s2 += x.x*m2.x + x.y*m2.y + x.z*m2.z + x.w*m2.w;
        }
#pragma unroll
        for (int o = 16; o; o >>= 1) {
            s0 += __shfl_down_sync(0xffffffffu, s0, o);
            s1 += __shfl_down_sync(0xffffffffu, s1, o);
            s2 += __shfl_down_sync(0xffffffffu, s2, o);
        }
        if (lane == 0)
            g_E[w] = make_float4(s0 + g_cbias[0], s1 + g_cbias[1], s2 + g_cbias[2], 0.f);
    }

    // ===== Phase 1b: table sweep — register double-buffer, M in regs =====
    {
        // per-lane slice of folded matrix: 6 float4 = 24 regs.
        // COHERENT loads (g_M was written this launch — nc path would be stale).
        const float4* gM4 = reinterpret_cast<const float4*>(g_M);
        const float4 m0a = gM4[lane],       m0b = gM4[32 + lane];
        const float4 m1a = gM4[64 + lane],  m1b = gM4[96 + lane];
        const float4 m2a = gM4[128 + lane], m2b = gM4[160 + lane];

        int p = gw;
        for (int i = 1; i < cnt; i++) {
            const int pn = gw + i * NWARPS;
            const float4* nb = tbl + (size_t)pn * 128;
            float4 B0 = __ldcs(nb + lane);
            float4 B1 = __ldcs(nb + 32 + lane);
            float4 B2 = __ldcs(nb + 64 + lane);
            float4 B3 = __ldcs(nb + 96 + lane);

            float r0 = dot8(A0, A1, m0a, m0b);
            float r1 = dot8(A0, A1, m1a, m1b);
            float r2 = dot8(A0, A1, m2a, m2b);
            float t0 = dot8(A2, A3, m0a, m0b);
            float t1 = dot8(A2, A3, m1a, m1b);
            float t2 = dot8(A2, A3, m2a, m2b);
#pragma unroll
            for (int o = 16; o; o >>= 1) {
                r0 += __shfl_xor_sync(0xffffffffu, r0, o);
                r1 += __shfl_xor_sync(0xffffffffu, r1, o);
                r2 += __shfl_xor_sync(0xffffffffu, r2, o);
                t0 += __shfl_xor_sync(0xffffffffu, t0, o);
                t1 += __shfl_xor_sync(0xffffffffu, t1, o);
                t2 += __shfl_xor_sync(0xffffffffu, t2, o);
            }
            if (lane < 2) {
                float4 v = (lane == 0) ? make_float4(r0, r1, r2, 0.f)
                                       : make_float4(t0, t1, t2, 0.f);
                g_P[2 * p + lane] = v;
            }
            A0 = B0; A1 = B1; A2 = B2; A3 = B3;
            p = pn;
        }
        // epilogue: last unit
        {
            float r0 = dot8(A0, A1, m0a, m0b);
            float r1 = dot8(A0, A1, m1a, m1b);
            float r2 = dot8(A0, A1, m2a, m2b);
            float t0 = dot8(A2, A3, m0a, m0b);
            float t1 = dot8(A2, A3, m1a, m1b);
            float t2 = dot8(A2, A3, m2a, m2b);
#pragma unroll
            for (int o = 16; o; o >>= 1) {
                r0 += __shfl_xor_sync(0xffffffffu, r0, o);
                r1 += __shfl_xor_sync(0xffffffffu, r1, o);
                r2 += __shfl_xor_sync(0xffffffffu, r2, o);
                t0 += __shfl_xor_sync(0xffffffffu, t0, o);
                t1 += __shfl_xor_sync(0xffffffffu, t1, o);
                t2 += __shfl_xor_sync(0xffffffffu, t2, o);
            }
            if (lane < 2) {
                float4 v = (lane == 0) ? make_float4(r0, r1, r2, 0.f)
                                       : make_float4(t0, t1, t2, 0.f);
                g_P[2 * p + lane] = v;
            }
        }
    }

    grid_bar(2 * GRID);   // ---- barrier B: g_P / g_E ready ----

    // ================= Phase 2: gather + relu + emit ==================
    {
        int q = bid * 107 + tid;
        if (tid < 107 && q < NSAMP / 4) {
            int i = q * 4;
            int c = i / (NB * NS);
            int b = (i - c * (NB * NS)) / NS;

            int4 sv = sampled[q];
            int  vb = c * BINS;
            float4 p0 = g_P[vb + sv.x];
            float4 p1 = g_P[vb + sv.y];
            float4 p2 = g_P[vb + sv.z];
            float4 p3 = g_P[vb + sv.w];
            float4 e  = g_E[b * N_CHROM + c];

            float4* o4 = reinterpret_cast<float4*>(out + 12 * (size_t)q);
            o4[0] = make_float4(fmaxf(p0.x + e.x, 0.f), fmaxf(p0.y + e.y, 0.f),
                                fmaxf(p0.z + e.z, 0.f), fmaxf(p1.x + e.x, 0.f));
            o4[1] = make_float4(fmaxf(p1.y + e.y, 0.f), fmaxf(p1.z + e.z, 0.f),
                                fmaxf(p2.x + e.x, 0.f), fmaxf(p2.y + e.y, 0.f));
            o4[2] = make_float4(fmaxf(p2.z + e.z, 0.f), fmaxf(p3.x + e.x, 0.f),
                                fmaxf(p3.y + e.y, 0.f), fmaxf(p3.z + e.z, 0.f));

            if (write_targets) {
                int4 tv = targets[q];
                reinterpret_cast<float4*>(out + 3 * NSAMP)[q] =
                    make_float4((float)tv.x, (float)tv.y, (float)tv.z, (float)tv.w);
            }
        }
    }

    // ---- final arrive: last arrival resets counter for graph replay ----
    __syncthreads();
    if (tid == 0) {
        unsigned prev = atomicAdd(&g_bar, 1u);
        if (prev + 1u == 3u * GRID) atomicExch(&g_bar, 0u);
    }
}

// ---------------------------------------------------------------------------
extern "C" void kernel_launch(void* const* d_in, const int* in_sizes, int n_in,
                              void* d_out, int out_size) {
    const float*  eos_emb = (const float*) d_in[0];
    const int4*   sampled = (const int4*)  d_in[1];
    const int4*   targets = (const int4*)  d_in[2];
    const float4* tbl     = (const float4*)d_in[3];
    const float*  Wbin    = (const float*) d_in[4];
    const float*  Weos    = (const float*) d_in[5];
    const float*  beos    = (const float*) d_in[6];
    const float*  Wfc     = (const float*) d_in[7];
    const float*  bfc     = (const float*) d_in[8];
    float* out = (float*)d_out;

    int write_targets = (out_size >= 4 * NSAMP) ? 1 : 0;
    k_fused<<<GRID, 256>>>(eos_emb, sampled, targets, tbl,
                           Wbin, Weos, beos, Wfc, bfc, out, write_targets);
}